// round 1
// baseline (speedup 1.0000x reference)
#include <cuda_runtime.h>
#include <cuda_bf16.h>
#include <math.h>

// CTC forward loss (reduction='none', zero_infinity=True), blank=0.
// Shapes fixed by problem: log_probs (T,N,C)=(512,512,80), targets (N,S)=(512,128),
// input_lengths (N,), target_lengths (N,). Output: (N,) float32 losses.
//
// Strategy: one CTA per batch element n; one thread per extended-lattice
// position s (L = 2S+1 = 257, blockDim = 288 = 9 warps). alpha kept in a
// double-buffered shared array (one __syncthreads per time step). Each thread
// also keeps its own alpha in a register (only neighbors read shared).
// Emission rows (C=80 floats per (t,n)) are software-pipelined through a
// double-buffered shared row (LDG one iteration ahead -> register -> STS).
//
// Exact prunings (warp-uniform branches; all threads still STS + BAR):
//  * t loop runs only to input_length[n] (reference freezes alpha afterwards).
//  * upper band s > min(2t+1, 2*tl): value is exactly NEG (-1e30 absorbs all
//    fp32 additions of O(1e3)), identical to reference / never read.
//  * lower band s < 2*tl-1-2*(len-1-t): cannot reach readout states
//    {2tl-1, 2tl}; dependency cone of in-band elements stays in-band.

#define NEGF (-1e30f)

constexpr int T_ = 512;
constexpr int N_ = 512;
constexpr int C_ = 80;
constexpr int S_ = 128;
constexpr int L_ = 2 * S_ + 1;   // 257
constexpr int NTH = 288;         // 9 warps, covers s in [0, 287]
constexpr int NC_ = N_ * C_;

__global__ __launch_bounds__(NTH)
void ctc_loss_kernel(const float* __restrict__ lp,
                     const int*   __restrict__ tgt,
                     const int*   __restrict__ ilen,
                     const int*   __restrict__ tlen,
                     float*       __restrict__ out)
{
    __shared__ float alpha[2][NTH + 4];  // alpha value for position s stored at [s+2]
    __shared__ float row[2][C_];         // emission log-prob rows, double buffered

    const int n   = blockIdx.x;
    const int s   = threadIdx.x;
    const int len = ilen[n];             // in [T/2, T]
    const int tl  = tlen[n];             // in [S/2, S]
    const int hi_cap = 2 * tl;           // readout states are 2tl and 2tl-1

    // Extended label for this lattice position + skip-transition permission.
    int  ext_s = 0;
    bool skip  = false;
    if (s < L_ && (s & 1)) {
        const int k = s >> 1;            // k in [0, S-1]
        ext_s = tgt[n * S_ + k];
        if (k >= 1) skip = (ext_s != tgt[n * S_ + k - 1]);
    }

    // Preload emission rows 0, 1 and prefetch row 2.
    const int nC = n * C_;
    float rnext = 0.0f;
    if (s < C_) {
        row[0][s] = lp[nC + s];
        row[1][s] = lp[min(1, len - 1) * NC_ + nC + s];
        rnext     = lp[min(2, len - 1) * NC_ + nC + s];
    }
    if (s < 2) { alpha[0][s] = NEGF; alpha[1][s] = NEGF; }
    __syncthreads();

    // alpha at t=0: only s=0 (blank) and s=1 (first label) reachable.
    float a = NEGF;
    if (s == 0)      a = row[0][0];
    else if (s == 1) a = row[0][ext_s];
    alpha[0][s + 2] = a;
    __syncthreads();

    const int wlo = s & ~31;             // warp-uniform position range
    const int whi = wlo + 31;

    for (int t = 1; t < len; ++t) {
        const int cur = t & 1;
        const int prv = cur ^ 1;

        // Stage row (t+1) from register to the buffer not in use this step,
        // then issue the load for row (t+2) (clamped; value unused at the tail).
        if (s < C_) {
            row[prv][s] = rnext;
            rnext = lp[min(t + 2, len - 1) * NC_ + nC + s];
        }

        const int hi = min(2 * t + 1, hi_cap);
        const int lo = hi_cap - 1 - 2 * (len - 1 - t);  // may be negative
        if (wlo <= hi && whi >= lo) {                   // warp-uniform branch
            const float am1 = alpha[prv][s + 1];        // alpha[s-1]
            const float am2 = skip ? alpha[prv][s] : NEGF;  // alpha[s-2]
            const float e   = row[cur][ext_s];
            // logsumexp(a, am1, am2): factor out the max (its exp is exactly 1).
            const float h   = fmaxf(a, am1);
            const float l   = fminf(a, am1);
            const float m   = fmaxf(h, am2);
            const float mid = fminf(h, am2);
            const float sum = 1.0f + __expf(mid - m) + __expf(l - m);
            a = m + __logf(sum) + e;
        }
        alpha[cur][s + 2] = a;
        __syncthreads();
    }

    if (s == 0) {
        const int fin = (len - 1) & 1;   // buffer written at the last step
        const float v1 = alpha[fin][2 * tl + 2];      // state 2*tl
        const float v2 = alpha[fin][2 * tl + 1];      // state 2*tl - 1
        const float m  = fmaxf(v1, v2);
        float loss = -(m + logf(expf(v1 - m) + expf(v2 - m)));
        // zero_infinity: non-finite or huge (infeasible) -> 0
        if (!isfinite(loss) || !(loss < 1e10f)) loss = 0.0f;
        out[n] = loss;
    }
}

extern "C" void kernel_launch(void* const* d_in, const int* in_sizes, int n_in,
                              void* d_out, int out_size)
{
    const float* lp   = (const float*)d_in[0];
    const int*   tgt  = (const int*)  d_in[1];
    const int*   ilen = (const int*)  d_in[2];
    const int*   tlen = (const int*)  d_in[3];
    float*       out  = (float*)      d_out;

    ctc_loss_kernel<<<out_size, NTH>>>(lp, tgt, ilen, tlen, out);
}